// round 2
// baseline (speedup 1.0000x reference)
#include <cuda_runtime.h>
#include <cuda_bf16.h>

// Fused separable 21-tap Gaussian blur with reflect padding.
// x: [32, 1, 1024, 1024] f32, k2d: [1,1,21,21] f32 (rank-1: k2d = u u^T).
// Tile: 128 (x) x 64 (y) outputs per block, 256 threads.
// Phase A: cooperative load of (64+20) x (128+20) input region into smem (reflect).
// Phase B: horizontal 21-tap conv -> htmp[84][128] in smem (register-blocked, 16 out/task).
// Phase C: vertical 21-tap conv -> global (register-blocked, 16 out/task, coalesced STG).

#define IMG 1024
#define TX 128
#define TY 64
#define R 10
#define KW 21
#define RAW_W 148           // TX + 2*R, multiple of 4 for float4 LDS
#define RAW_H 84            // TY + 2*R
#define RAW_ELEMS (RAW_H * RAW_W)     // 12432
#define HTMP_ELEMS (RAW_H * TX)       // 10752
#define SMEM_BYTES ((RAW_ELEMS + HTMP_ELEMS) * 4)   // 92736

__device__ __forceinline__ int reflect_idx(int i) {
    // jnp.pad mode='reflect' (edge not repeated): -1 -> 1, 1024 -> 1022
    i = (i < 0) ? -i : i;
    i = (i > IMG - 1) ? (2 * (IMG - 1) - i) : i;
    return i;
}

__global__ void __launch_bounds__(256, 2)
gauss21_kernel(const float* __restrict__ x, const float* __restrict__ k2d,
               float* __restrict__ out) {
    extern __shared__ float sm[];
    float* raw  = sm;                    // [RAW_H][RAW_W]
    float* htmp = sm + RAW_ELEMS;        // [RAW_H][TX]

    const int tid = threadIdx.x;
    const int x0 = blockIdx.x * TX;
    const int y0 = blockIdx.y * TY;
    const long b = blockIdx.z;
    const float* __restrict__ xb = x + b * (long)(IMG * IMG);
    float* __restrict__ ob = out + b * (long)(IMG * IMG);

    // Extract the 1D separable factor: k2d[i][j] = u[i]*u[j]
    // u[j] = k2d[10][j] / sqrt(k2d[10][10]); row 10 starts at 210, center 220.
    float u[KW];
    {
        const float inv = rsqrtf(__ldg(&k2d[220]));
#pragma unroll
        for (int j = 0; j < KW; j++) u[j] = __ldg(&k2d[210 + j]) * inv;
    }

    // ---- Phase A: load input region with reflect indexing ----
    for (int idx = tid; idx < RAW_ELEMS; idx += 256) {
        const int r = idx / RAW_W;
        const int c = idx - r * RAW_W;
        const int gy = reflect_idx(y0 - R + r);
        const int gx = reflect_idx(x0 - R + c);
        raw[idx] = __ldg(&xb[gy * IMG + gx]);
    }
    __syncthreads();

    // ---- Phase B: horizontal conv. 84 rows x 8 segments of 16 outputs = 672 tasks ----
    for (int task = tid; task < RAW_H * 8; task += 256) {
        const int row = task >> 3;
        const int seg = (task & 7) << 4;            // output col base within tile
        const float* rp = &raw[row * RAW_W + seg];  // 16B-aligned (row*148, seg*16)

        float w[36];
#pragma unroll
        for (int i = 0; i < 9; i++) {
            const float4 v = *(const float4*)(rp + 4 * i);
            w[4 * i + 0] = v.x; w[4 * i + 1] = v.y;
            w[4 * i + 2] = v.z; w[4 * i + 3] = v.w;
        }

        float* hp = &htmp[row * TX + seg];
#pragma unroll
        for (int c = 0; c < 16; c++) {
            float a = u[0] * w[c];
#pragma unroll
            for (int j = 1; j < KW; j++) a = fmaf(u[j], w[c + j], a);
            hp[c] = a;
        }
    }
    __syncthreads();

    // ---- Phase C: vertical conv. 128 cols x 4 row-blocks of 16 = 512 tasks ----
#pragma unroll
    for (int it = 0; it < 2; it++) {
        const int task = tid + it * 256;
        const int col = task & (TX - 1);
        const int rb  = (task >> 7) << 4;           // 0,16,32,48

        float v[36];
#pragma unroll
        for (int i = 0; i < 36; i++) v[i] = htmp[(rb + i) * TX + col];

        float* op = &ob[(long)(y0 + rb) * IMG + x0 + col];
#pragma unroll
        for (int o = 0; o < 16; o++) {
            float a = u[0] * v[o];
#pragma unroll
            for (int j = 1; j < KW; j++) a = fmaf(u[j], v[o + j], a);
            op[(long)o * IMG] = a;
        }
    }
}

extern "C" void kernel_launch(void* const* d_in, const int* in_sizes, int n_in,
                              void* d_out, int out_size) {
    const float* x   = (const float*)d_in[0];
    const float* k2d = (const float*)d_in[1];
    float* out = (float*)d_out;

    cudaFuncSetAttribute(gauss21_kernel,
                         cudaFuncAttributeMaxDynamicSharedMemorySize, SMEM_BYTES);

    dim3 grid(IMG / TX, IMG / TY, 32);
    dim3 block(256);
    gauss21_kernel<<<grid, block, SMEM_BYTES>>>(x, k2d, out);
}